// round 3
// baseline (speedup 1.0000x reference)
#include <cuda_runtime.h>
#include <cuda_bf16.h>

// LengthRegulator: B=16, T=512, D=384, target_len=4096, fp32.
// out[b, t, :] = x[b, idx(b,t), :], idx = searchsorted_right(cumsum(max(dur,1)), t),
// clamped to T-1; zero where t >= total(b).
//
// R2: exploit idx monotonicity (advances <=1 per output row) — each block's 64 output
// rows read a CONTIGUOUS range of <=64 (avg ~9) source rows. Stage that range in
// dynamic smem with one coalesced sweep, then hot loop = LDS.128 -> STG.128 with
// linear store addressing. Kills ~85% of L1 gather-read wavefronts.

namespace {

constexpr int B  = 16;
constexpr int T  = 512;
constexpr int D  = 384;
constexpr int TL = 4096;
constexpr int D4 = D / 4;        // 96 float4 per row
constexpr int ROWS = 64;         // output rows per block
constexpr int THREADS = 512;
constexpr int SMEM_ROWS_BYTES = ROWS * D4 * (int)sizeof(float4);  // 96 KB

__global__ __launch_bounds__(THREADS, 2)
void length_regulator_kernel(const float* __restrict__ x,
                             const int* __restrict__ durations,
                             float* __restrict__ out)
{
    extern __shared__ float4 s_rows[];      // ROWS * D4 float4 (dynamic, 96 KB)
    __shared__ int s_cum[T];
    __shared__ int s_warp[16];
    __shared__ int s_off[ROWS];             // smem float4 base offset per row, -1 => zeros
    __shared__ int s_lo, s_n;

    const int b    = blockIdx.y;
    const int tid  = threadIdx.x;
    const int lane = tid & 31;
    const int w    = tid >> 5;

    // ---- inclusive scan of max(dur,1) over T=512 (one element per thread) ----
    int d = durations[b * T + tid];
    d = (d < 1) ? 1 : d;

    int v = d;
    #pragma unroll
    for (int o = 1; o < 32; o <<= 1) {
        int n = __shfl_up_sync(0xffffffffu, v, o);
        if (lane >= o) v += n;
    }
    if (lane == 31) s_warp[w] = v;
    __syncthreads();
    if (w == 0 && lane < 16) {
        int wv = s_warp[lane];
        #pragma unroll
        for (int o = 1; o < 16; o <<= 1) {
            int n = __shfl_up_sync(0x0000ffffu, wv, o);
            if (lane >= o) wv += n;
        }
        s_warp[lane] = wv;
    }
    __syncthreads();
    const int add = (w > 0) ? s_warp[w - 1] : 0;
    s_cum[tid] = v + add;
    __syncthreads();

    const int total = s_cum[T - 1];
    const int t0 = blockIdx.x * ROWS;

    // ---- binary search (searchsorted right) for this block's 64 rows ----
    if (tid < ROWS) {
        const int t = t0 + tid;
        int lo = 0, hi = T;                  // first j with cum[j] > t
        while (lo < hi) {
            int mid = (lo + hi) >> 1;
            if (s_cum[mid] <= t) lo = mid + 1; else hi = mid;
        }
        int idx = (lo < T - 1) ? lo : (T - 1);
        s_off[tid] = (t < total) ? idx : -1;   // temporarily hold source row index
    }
    __syncthreads();

    if (tid == 0) {
        int nv = total - t0;                  // number of valid rows in this block
        nv = (nv < 0) ? 0 : (nv > ROWS ? ROWS : nv);
        int lo = (nv > 0) ? s_off[0] : 0;
        int hi = (nv > 0) ? s_off[nv - 1] : -1;
        s_lo = lo;
        s_n  = hi - lo + 1;                   // 0 when no valid rows
    }
    __syncthreads();

    const int lo = s_lo;
    const int n  = s_n;                       // contiguous source rows needed (<= 64)

    // convert row indices to smem float4 offsets
    if (tid < ROWS) {
        int idx = s_off[tid];
        s_off[tid] = (idx >= 0) ? (idx - lo) * D4 : -1;
    }

    // ---- stage contiguous source range [lo, lo+n) into smem: one coalesced sweep ----
    const float4* __restrict__ xb =
        reinterpret_cast<const float4*>(x) + ((size_t)b * T + lo) * D4;
    for (int i = tid; i < n * D4; i += THREADS) {
        s_rows[i] = xb[i];
    }
    __syncthreads();

    // ---- hot loop: 64 rows x 96 float4 = 6144 float4, 12 per thread ----
    // Output addressing is LINEAR (i), since rows within a block are contiguous.
    float4* __restrict__ ob =
        reinterpret_cast<float4*>(out) + ((size_t)b * TL + t0) * D4;

    const float4 zero4 = make_float4(0.f, 0.f, 0.f, 0.f);
    #pragma unroll
    for (int k = 0; k < (ROWS * D4) / THREADS; ++k) {
        const int i = k * THREADS + tid;
        const int r = i / D4;
        const int c = i - r * D4;
        const int off = s_off[r];
        float4 val = (off >= 0) ? s_rows[off + c] : zero4;
        ob[i] = val;
    }
}

} // namespace

extern "C" void kernel_launch(void* const* d_in, const int* in_sizes, int n_in,
                              void* d_out, int out_size)
{
    const float* x         = (const float*)d_in[0];
    const int*   durations = (const int*)d_in[1];
    float*       out       = (float*)d_out;

    cudaFuncSetAttribute(length_regulator_kernel,
                         cudaFuncAttributeMaxDynamicSharedMemorySize,
                         SMEM_ROWS_BYTES);

    dim3 grid(TL / ROWS, B);   // (64, 16)
    length_regulator_kernel<<<grid, THREADS, SMEM_ROWS_BYTES>>>(x, durations, out);
}

// round 5
// speedup vs baseline: 1.2653x; 1.2653x over previous
#include <cuda_runtime.h>
#include <cuda_bf16.h>

// LengthRegulator: B=16, T=512, D=384, target_len=4096, fp32.
// out[b, t, :] = x[b, idx(b,t), :], idx = searchsorted_right(cumsum(max(dur,1)), t),
// clamped to T-1; zero where t >= total(b).
//
// R3: revert smem staging (R2 regression). Direct LDG->STG like R1 but:
//  - 256-thread blocks, 32 rows/block, grid (128,16)=2048 blocks
//  - __launch_bounds__(256, 6) -> more CTAs/SM, more warps in flight
//  - warp-per-row mapping: no div in hot loop, 1 idx broadcast per row

namespace {

constexpr int B  = 16;
constexpr int T  = 512;
constexpr int D  = 384;
constexpr int TL = 4096;
constexpr int D4 = D / 4;        // 96 float4 per row
constexpr int ROWS = 32;         // output rows per block
constexpr int THREADS = 256;
constexpr int ROWS_PER_WARP = ROWS / (THREADS / 32);  // 4

__global__ __launch_bounds__(THREADS, 6)
void length_regulator_kernel(const float* __restrict__ x,
                             const int* __restrict__ durations,
                             float* __restrict__ out)
{
    __shared__ int s_cum[T];
    __shared__ int s_warp[8];
    __shared__ int s_idx[ROWS];   // source row per output row, -1 => zeros

    const int b    = blockIdx.y;
    const int tid  = threadIdx.x;
    const int lane = tid & 31;
    const int w    = tid >> 5;

    // ---- inclusive scan of max(dur,1) over T=512, 2 elements per thread ----
    const int2 dp = reinterpret_cast<const int2*>(durations + b * T)[tid];
    const int d0 = (dp.x < 1) ? 1 : dp.x;
    const int d1 = (dp.y < 1) ? 1 : dp.y;

    int v = d0 + d1;                        // pair sum
    #pragma unroll
    for (int o = 1; o < 32; o <<= 1) {
        int n = __shfl_up_sync(0xffffffffu, v, o);
        if (lane >= o) v += n;
    }
    if (lane == 31) s_warp[w] = v;
    __syncthreads();
    if (w == 0 && lane < 8) {
        int wv = s_warp[lane];
        #pragma unroll
        for (int o = 1; o < 8; o <<= 1) {
            int n = __shfl_up_sync(0x000000ffu, wv, o);
            if (lane >= o) wv += n;
        }
        s_warp[lane] = wv;
    }
    __syncthreads();
    const int base = (w > 0) ? s_warp[w - 1] : 0;
    const int c1 = base + v;                // cum at element 2*tid+1 (inclusive)
    s_cum[2 * tid]     = c1 - d1;           // cum at element 2*tid
    s_cum[2 * tid + 1] = c1;
    __syncthreads();

    const int total = s_cum[T - 1];
    const int t0 = blockIdx.x * ROWS;

    // ---- binary search (searchsorted right) for this block's 32 rows ----
    if (tid < ROWS) {
        const int t = t0 + tid;
        int lo = 0, hi = T;                  // first j with cum[j] > t
        while (lo < hi) {
            int mid = (lo + hi) >> 1;
            if (s_cum[mid] <= t) lo = mid + 1; else hi = mid;
        }
        int idx = (lo < T - 1) ? lo : (T - 1);
        s_idx[tid] = (t < total) ? idx : -1;
    }
    __syncthreads();

    // ---- hot loop: warp w handles rows [w*4, w*4+4); 3 float4 per lane per row ----
    const float4* __restrict__ xb =
        reinterpret_cast<const float4*>(x) + (size_t)b * T * D4;
    float4* __restrict__ ob =
        reinterpret_cast<float4*>(out) + ((size_t)b * TL + t0) * D4;

    const float4 zero4 = make_float4(0.f, 0.f, 0.f, 0.f);
    const int r0 = w * ROWS_PER_WARP;

    #pragma unroll
    for (int k = 0; k < ROWS_PER_WARP; ++k) {
        const int r   = r0 + k;
        const int idx = s_idx[r];            // broadcast LDS
        float4* __restrict__ orow = ob + (size_t)r * D4 + lane;
        if (idx >= 0) {
            const float4* __restrict__ xrow = xb + (size_t)idx * D4 + lane;
            float4 v0 = xrow[0];
            float4 v1 = xrow[32];
            float4 v2 = xrow[64];
            orow[0]  = v0;
            orow[32] = v1;
            orow[64] = v2;
        } else {
            orow[0]  = zero4;
            orow[32] = zero4;
            orow[64] = zero4;
        }
    }
}

} // namespace

extern "C" void kernel_launch(void* const* d_in, const int* in_sizes, int n_in,
                              void* d_out, int out_size)
{
    const float* x         = (const float*)d_in[0];
    const int*   durations = (const int*)d_in[1];
    float*       out       = (float*)d_out;

    dim3 grid(TL / ROWS, B);   // (128, 16)
    length_regulator_kernel<<<grid, THREADS>>>(x, durations, out);
}